// round 10
// baseline (speedup 1.0000x reference)
#include <cuda_runtime.h>
#include <cuda_bf16.h>
#include <cstdint>

#define NNODES 20000
#define NEDGES 640000
#define IND    256
#define HID    128
#define NG     64

#define NFG    4            // feature groups (64 cols each)
#define NKB    35           // split-K blocks per feature group
#define NCTA   (NFG * NKB)  // 140 CTAs, all co-resident on 148 SMs
#define NBN    576          // nodes per split-K block
#define NST    36           // stages of 16 nodes

// ---------------- device scratch ----------------
__device__ __align__(16) unsigned g_Cp[NNODES * 16];          // packed u8 counts [node][g]
__device__ __align__(16) int      g_outdeg[NNODES];
__device__ __align__(16) int      g_cnt[NG];
__device__ __align__(16) float    g_part[NFG][NKB][128][64];  // split-K partials (4.6 MB)
__device__ __align__(16) float    g_XF[128][IND];             // pooled (rows<64 src, >=64 dst)
__device__ __align__(16) float    g_P[2][128][HID];           // layer activations
__device__ volatile unsigned      g_bar[4];                   // phase barriers

// ---------------- helpers ----------------
__device__ __forceinline__ uint32_t f2tf32(float v) {
    uint32_t t;
    asm("cvt.rna.tf32.f32 %0, %1;" : "=r"(t) : "f"(v));
    return t;
}
__device__ __forceinline__ void mma_tf32(float* d, uint32_t a0, uint32_t a1, uint32_t a2,
                                         uint32_t a3, uint32_t b0, uint32_t b1) {
    asm volatile(
        "mma.sync.aligned.m16n8k8.row.col.f32.tf32.tf32.f32 "
        "{%0,%1,%2,%3},{%4,%5,%6,%7},{%8,%9},{%0,%1,%2,%3};"
        : "+f"(d[0]), "+f"(d[1]), "+f"(d[2]), "+f"(d[3])
        : "r"(a0), "r"(a1), "r"(a2), "r"(a3), "r"(b0), "r"(b1));
}
// B tile [k=16][n=64] f32; float4 at (k, r8, group) grabs n-blocks group*4..+3 col r8
__device__ __forceinline__ uint32_t bofB64(int k, int n) {
    int nq = n & 7, nb = n >> 3;
    int slot = (nq ^ k) & 7;
    return (uint32_t)(k * 256 + slot * 32 + (nb >> 2) * 16 + (nb & 3) * 4);
}
// A tile transposed [k=16][m=128] f32, swizzled for LDS.32 a-frags (verified R9)
__device__ __forceinline__ uint32_t bofA(int k, int m) {
    int mb  = m >> 2;
    int blk = (mb & 24) | (((mb & 7) ^ ((k & 3) << 1)) & 7);
    return (uint32_t)(k * 512 + blk * 16 + (m & 3) * 4);
}

// ---------------- small kernels ----------------
__global__ void zero_k() {
    int i = blockIdx.x * blockDim.x + threadIdx.x;
    uint4 zu = make_uint4(0u, 0u, 0u, 0u);
    int4  zi = make_int4(0, 0, 0, 0);
    if (i < NNODES * 16 / 4) ((uint4*)g_Cp)[i] = zu;
    if (i < NNODES / 4)      ((int4*)g_outdeg)[i] = zi;
    if (i < NG / 4)          ((int4*)g_cnt)[i] = zi;
    if (i < 4)               g_bar[i] = 0u;
}

__global__ void count_k(const int* __restrict__ src, const int* __restrict__ dst,
                        const int* __restrict__ batch) {
    __shared__ int hist[NG];
    int t = threadIdx.x;
    if (t < NG) hist[t] = 0;
    __syncthreads();
    int e4 = blockIdx.x * blockDim.x + t;
    int4 s4 = ((const int4*)src)[e4];
    int4 d4 = ((const int4*)dst)[e4];
    int ss[4] = {s4.x, s4.y, s4.z, s4.w};
    int dd[4] = {d4.x, d4.y, d4.z, d4.w};
#pragma unroll
    for (int u = 0; u < 4; u++) {
        int g = batch[ss[u]];
        atomicAdd(&g_Cp[dd[u] * 16 + (g >> 2)], 1u << ((g & 3) * 8));
        atomicAdd(&g_outdeg[ss[u]], 1);
        atomicAdd(&hist[g], 1);
    }
    __syncthreads();
    if (t < NG && hist[t]) atomicAdd(&g_cnt[t], hist[t]);
}

// ---------------- the fused persistent kernel ----------------
__global__ void __launch_bounds__(512, 1)
fused_k(const float* __restrict__ x, const int* __restrict__ batch,
        const float* __restrict__ W0, const float* __restrict__ b0p,
        const float* __restrict__ W1, const float* __restrict__ b1p,
        const float* __restrict__ W2, const float* __restrict__ b2p,
        float* __restrict__ out) {
    __shared__ __align__(16) float Bsm[2][16 * 64];    // 2 x 4 KB
    __shared__ __align__(16) float Atr[2][16 * 128];   // 2 x 8 KB
    __shared__ float As[32][17];
    __shared__ float Ws[16][17];

    const uint8_t* C8 = (const uint8_t*)g_Cp;
    int b    = blockIdx.x;
    int tid  = threadIdx.x;
    int lane = tid & 31;
    int warp = tid >> 5;

    auto gsync = [&](int ph) {
        __syncthreads();
        __threadfence();
        if (tid == 0) {
            atomicAdd((unsigned*)&g_bar[ph], 1u);
            while (g_bar[ph] < NCTA) { }
        }
        __syncthreads();
    };

    // ================= phase 1: split GEMM =================
    {
        int fg = b / NKB;
        int kb = b - fg * NKB;
        int F0 = fg * 64;
        int n0 = kb * NBN;

        int wm = warp & 7;     // m-tile rows wm*16..+15
        int wn = warp >> 3;    // n-group 0/1 (cols wn*32..+31)
        int kq = lane & 3;
        int r8 = lane >> 2;

        int ma = tid & 127;    // A-staging row
        int kh = tid >> 7;     // A-staging k quarter

        float acc[4][4];
#pragma unroll
        for (int i = 0; i < 4; i++)
#pragma unroll
            for (int j = 0; j < 4; j++) acc[i][j] = 0.f;

        const float2* x2 = (const float2*)x;

        float2 pv;
        float  pa[4];
        auto prefetch = [&](int s) {
            int nx = n0 + s * 16 + warp;
            pv = (nx < NNODES) ? x2[(size_t)nx * 128 + (F0 >> 1) + lane]
                               : make_float2(0.f, 0.f);
#pragma unroll
            for (int j = 0; j < 4; j++) {
                int na = n0 + s * 16 + kh * 4 + j;
                float v = 0.f;
                if (na < NNODES) {
                    if (ma < NG) {
                        v = (float)C8[na * 64 + ma];
                    } else {
                        int g = ma - NG;
                        if (batch[na] == g) v = (float)g_outdeg[na];
                    }
                }
                pa[j] = v;
            }
        };
        auto stage = [&](int buf) {
            char* Bb = (char*)Bsm[buf];
            char* Ab = (char*)Atr[buf];
            *(uint32_t*)(Bb + bofB64(warp, lane * 2))     = f2tf32(pv.x);
            *(uint32_t*)(Bb + bofB64(warp, lane * 2 + 1)) = f2tf32(pv.y);
#pragma unroll
            for (int j = 0; j < 4; j++)
                *(uint32_t*)(Ab + bofA(kh * 4 + j, ma)) = f2tf32(pa[j]);
        };

        prefetch(0);
        stage(0);

        for (int s = 0; s < NST; s++) {
            __syncthreads();
            int buf = s & 1;
            if (s + 1 < NST) prefetch(s + 1);

            const char* Ab = (const char*)Atr[buf];
            const char* Bb = (const char*)Bsm[buf];
#pragma unroll
            for (int ko = 0; ko < 16; ko += 8) {
                int k0v = ko + kq, k1v = ko + 4 + kq;
                uint32_t a0 = *(const uint32_t*)(Ab + bofA(k0v, wm * 16 + r8));
                uint32_t a1 = *(const uint32_t*)(Ab + bofA(k0v, wm * 16 + r8 + 8));
                uint32_t a2 = *(const uint32_t*)(Ab + bofA(k1v, wm * 16 + r8));
                uint32_t a3 = *(const uint32_t*)(Ab + bofA(k1v, wm * 16 + r8 + 8));
                float4 f0 = *(const float4*)(Bb + (uint32_t)(k0v * 256 + (((r8 ^ k0v) & 7) * 32) + wn * 16));
                float4 f1 = *(const float4*)(Bb + (uint32_t)(k1v * 256 + (((r8 ^ k1v) & 7) * 32) + wn * 16));
                const float b0v[4] = {f0.x, f0.y, f0.z, f0.w};
                const float b1v[4] = {f1.x, f1.y, f1.z, f1.w};
#pragma unroll
                for (int t = 0; t < 4; t++)
                    mma_tf32(acc[t], a0, a1, a2, a3,
                             __float_as_uint(b0v[t]), __float_as_uint(b1v[t]));
            }
            if (s + 1 < NST) stage((s + 1) & 1);
        }

        int r0 = wm * 16 + r8;
#pragma unroll
        for (int t = 0; t < 4; t++) {
            int fl = (wn * 4 + t) * 8 + kq * 2;
            *(float2*)&g_part[fg][kb][r0][fl]     = make_float2(acc[t][0], acc[t][1]);
            *(float2*)&g_part[fg][kb][r0 + 8][fl] = make_float2(acc[t][2], acc[t][3]);
        }
    }
    gsync(0);

    // ================= phase 2: fold + normalize -> XF =================
    {
        int gt = b * 512 + tid;
        if (gt < 128 * IND) {
            int r  = gt >> 8;
            int f  = gt & 255;
            int fg = f >> 6;
            int fl = f & 63;
            const float* p = &g_part[fg][0][r][fl];
            float v[NKB];
#pragma unroll
            for (int q = 0; q < NKB; q++) v[q] = p[(size_t)q * 128 * 64];
            float s0 = 0.f, s1 = 0.f, s2 = 0.f, s3 = 0.f;
            int q = 0;
#pragma unroll
            for (; q + 4 <= NKB; q += 4) {
                s0 += v[q]; s1 += v[q + 1]; s2 += v[q + 2]; s3 += v[q + 3];
            }
            float acc = (s0 + s1) + (s2 + s3);
            for (; q < NKB; q++) acc += v[q];
            int g = r & 63;
            int cnt = g_cnt[g];
            float inv = cnt > 0 ? 1.0f / (float)cnt : 0.0f;
            int row = (r < NG) ? (NG + r) : (r - NG);
            g_XF[row][f] = acc * inv;
        }
    }
    gsync(1);

    // ================= phases 3-5: head layers =================
#pragma unroll
    for (int layer = 0; layer < 3; layer++) {
        if (b < 32) {
            int rt = b >> 3, ct = b & 7;
            int ty = tid >> 4, tx = tid & 15;
            int r = rt * 32 + ty;
            int c = ct * 16 + tx;
            const float* W  = (layer == 0) ? W0 : (layer == 1) ? W1 : W2;
            const float* bs = (layer == 0) ? b0p : (layer == 1) ? b1p : b2p;
            int K = (layer == 0) ? IND : HID;
            float acc = 0.f;
            for (int k0 = 0; k0 < K; k0 += 16) {
                float av;
                if (layer == 0)      av = g_XF[r][k0 + tx];
                else if (layer == 1) av = g_P[0][r][k0 + tx];
                else                 av = g_P[1][r][k0 + tx];
                As[ty][tx] = av;
                if (ty < 16) Ws[ty][tx] = W[(k0 + ty) * HID + c];
                __syncthreads();
#pragma unroll
                for (int kk = 0; kk < 16; kk++) acc += As[ty][kk] * Ws[kk][tx];
                __syncthreads();
            }
            int g = r & (NG - 1);
            float flag = g_cnt[g] > 0 ? 1.0f : 0.0f;
            float v = (acc + bs[c]) * flag;
            if (layer < 2) g_P[layer][r][c] = v;
            int col = layer * 256 + ((r < NG) ? 0 : HID) + c;
            out[g * 768 + col] = v;
        }
        if (layer < 2) gsync(2 + layer);
    }
}

// ---------------- launcher ----------------
extern "C" void kernel_launch(void* const* d_in, const int* in_sizes, int n_in,
                              void* d_out, int out_size) {
    const float* x     = (const float*)d_in[0];
    const int*   eidx  = (const int*)d_in[1];
    const int*   batch = (const int*)d_in[2];
    const float* W0 = (const float*)d_in[3];
    const float* b0 = (const float*)d_in[4];
    const float* W1 = (const float*)d_in[5];
    const float* b1 = (const float*)d_in[6];
    const float* W2 = (const float*)d_in[7];
    const float* b2 = (const float*)d_in[8];
    float* out = (float*)d_out;

    const int* src = eidx;
    const int* dst = eidx + NEDGES;

    zero_k<<<(NNODES * 16 / 4 + 255) / 256, 256>>>();
    count_k<<<NEDGES / 4 / 256, 256>>>(src, dst, batch);
    fused_k<<<NCTA, 512>>>(x, batch, W0, b0, W1, b1, W2, b2, out);
}

// round 11
// speedup vs baseline: 1.5917x; 1.5917x over previous
#include <cuda_runtime.h>
#include <cuda_bf16.h>
#include <cstdint>

#define NNODES 20000
#define NEDGES 640000
#define IND    256
#define HID    128
#define NG     64

#define KBLK   139          // CTAs in split-K GEMM
#define KPADB  140          // padded partial count (index 139 stays zero forever)
#define NB     144          // nodes per CTA
#define NST    9            // stages of 16 nodes
#define TCTA   128          // tail_k CTAs

// ---------------- device scratch (zero-initialized at module load) ----------------
__device__ __align__(16) unsigned g_Cp[NNODES * 16];       // packed u8 counts [node][g]
__device__ __align__(16) int      g_outdeg[NNODES];
__device__ __align__(16) int      g_cnt[NG];               // atomic accumulator (self-cleaned)
__device__ __align__(16) int      g_cntR[NG];              // stable copy read by tail
__device__ __align__(16) float    g_part[KPADB][128][IND]; // split-K partials
__device__ __align__(16) float    g_XF[128][IND];          // pooled features
__device__ __align__(16) float    g_P[2][128][HID];        // layer activations
__device__ volatile unsigned      g_tbar[4];               // tail barriers (reset by mm_k)

// ---------------- helpers ----------------
__device__ __forceinline__ uint32_t f2tf32(float v) {
    uint32_t t;
    asm("cvt.rna.tf32.f32 %0, %1;" : "=r"(t) : "f"(v));
    return t;
}
__device__ __forceinline__ void mma_tf32(float* d, uint32_t a0, uint32_t a1, uint32_t a2,
                                         uint32_t a3, uint32_t b0, uint32_t b1) {
    asm volatile(
        "mma.sync.aligned.m16n8k8.row.col.f32.tf32.tf32.f32 "
        "{%0,%1,%2,%3},{%4,%5,%6,%7},{%8,%9},{%0,%1,%2,%3};"
        : "+f"(d[0]), "+f"(d[1]), "+f"(d[2]), "+f"(d[3])
        : "r"(a0), "r"(a1), "r"(a2), "r"(a3), "r"(b0), "r"(b1));
}
// B smem layout (verified R9): element (k, n) of the 16x256 x-tile
__device__ __forceinline__ uint32_t bofB(int k, int n) {
    int nq  = n & 7;
    int nb  = n >> 3;
    int blk = ((nb >> 2) ^ nq ^ ((k & 3) << 1)) & 7;
    return (uint32_t)(k * 1024 + nq * 128 + blk * 16 + (nb & 3) * 4);
}
// A smem layout (verified R9): transposed [k][m]
__device__ __forceinline__ uint32_t bofA(int k, int m) {
    int mb  = m >> 2;
    int blk = (mb & 24) | (((mb & 7) ^ ((k & 3) << 1)) & 7);
    return (uint32_t)(k * 512 + blk * 16 + (m & 3) * 4);
}

// ---------------- kernels ----------------
__global__ void count_k(const int* __restrict__ src, const int* __restrict__ dst,
                        const int* __restrict__ batch) {
    __shared__ int hist[NG];
    int t = threadIdx.x;
    if (t < NG) hist[t] = 0;
    __syncthreads();
    int e4 = blockIdx.x * blockDim.x + t;
    int4 s4 = ((const int4*)src)[e4];
    int4 d4 = ((const int4*)dst)[e4];
    int ss[4] = {s4.x, s4.y, s4.z, s4.w};
    int dd[4] = {d4.x, d4.y, d4.z, d4.w};
#pragma unroll
    for (int u = 0; u < 4; u++) {
        int g = batch[ss[u]];
        atomicAdd(&g_Cp[dd[u] * 16 + (g >> 2)], 1u << ((g & 3) * 8));
        atomicAdd(&g_outdeg[ss[u]], 1);
        atomicAdd(&hist[g], 1);
    }
    __syncthreads();
    if (t < NG && hist[t]) atomicAdd(&g_cnt[t], hist[t]);
}

// TF32 pooling GEMM (verified R9) + self-cleaning epilogue
__global__ void __launch_bounds__(512, 1) mm_k(const float* __restrict__ x,
                                               const int* __restrict__ batch) {
    __shared__ __align__(16) float Bsm[2][16 * 256];
    __shared__ __align__(16) float Atr[2][16 * 128];

    const uint8_t* C8 = (const uint8_t*)g_Cp;
    int b    = blockIdx.x;
    int n0   = b * NB;
    int tid  = threadIdx.x;
    int lane = tid & 31;
    int warp = tid >> 5;
    int wm   = warp & 7;
    int wn   = warp >> 3;
    int kq   = lane & 3;
    int r8   = lane >> 2;

    int kx = warp;
    int cx = lane;
    int ma = tid & 127;
    int kh = tid >> 7;

    float acc[16][4];
#pragma unroll
    for (int i = 0; i < 16; i++)
#pragma unroll
        for (int j = 0; j < 4; j++) acc[i][j] = 0.f;

    const float4* x4 = (const float4*)x;

    float4 pv0, pv1;
    float  pa[4];
    auto prefetch = [&](int s) {
        int nx = n0 + s * 16 + kx;
        if (nx < NNODES) {
            pv0 = x4[(size_t)nx * 64 + cx * 2];
            pv1 = x4[(size_t)nx * 64 + cx * 2 + 1];
        } else {
            pv0 = make_float4(0.f, 0.f, 0.f, 0.f);
            pv1 = pv0;
        }
#pragma unroll
        for (int j = 0; j < 4; j++) {
            int na = n0 + s * 16 + kh * 4 + j;
            float v = 0.f;
            if (na < NNODES) {
                if (ma < NG) {
                    v = (float)C8[na * 64 + ma];
                } else {
                    int g = ma - NG;
                    if (batch[na] == g) v = (float)g_outdeg[na];
                }
            }
            pa[j] = v;
        }
    };
    auto stage = [&](int buf) {
        float vs[8] = {pv0.x, pv0.y, pv0.z, pv0.w, pv1.x, pv1.y, pv1.z, pv1.w};
        char* Bb = (char*)Bsm[buf];
        char* Ab = (char*)Atr[buf];
#pragma unroll
        for (int j = 0; j < 8; j++)
            *(uint32_t*)(Bb + bofB(kx, cx * 8 + j)) = f2tf32(vs[j]);
#pragma unroll
        for (int j = 0; j < 4; j++)
            *(uint32_t*)(Ab + bofA(kh * 4 + j, ma)) = f2tf32(pa[j]);
    };

    prefetch(0);
    stage(0);

    for (int s = 0; s < NST; s++) {
        __syncthreads();
        int buf = s & 1;
        if (s + 1 < NST) prefetch(s + 1);

        const char* Ab = (const char*)Atr[buf];
        const char* Bb = (const char*)Bsm[buf];
#pragma unroll
        for (int ko = 0; ko < 16; ko += 8) {
            uint32_t a0 = *(const uint32_t*)(Ab + bofA(ko + kq,     wm * 16 + r8));
            uint32_t a1 = *(const uint32_t*)(Ab + bofA(ko + kq,     wm * 16 + r8 + 8));
            uint32_t a2 = *(const uint32_t*)(Ab + bofA(ko + 4 + kq, wm * 16 + r8));
            uint32_t a3 = *(const uint32_t*)(Ab + bofA(ko + 4 + kq, wm * 16 + r8 + 8));
#pragma unroll
            for (int g0 = 0; g0 < 4; g0++) {
                int nbase = (wn * 16 + g0 * 4) * 8 + r8;
                float4 f0 = *(const float4*)(Bb + bofB(ko + kq,     nbase));
                float4 f1 = *(const float4*)(Bb + bofB(ko + 4 + kq, nbase));
                const float b0v[4] = {f0.x, f0.y, f0.z, f0.w};
                const float b1v[4] = {f1.x, f1.y, f1.z, f1.w};
#pragma unroll
                for (int t = 0; t < 4; t++) {
                    mma_tf32(acc[g0 * 4 + t], a0, a1, a2, a3,
                             __float_as_uint(b0v[t]), __float_as_uint(b1v[t]));
                }
            }
        }
        if (s + 1 < NST) stage((s + 1) & 1);
    }

    int r0 = wm * 16 + r8;
    int c0 = wn * 128 + kq * 2;
#pragma unroll
    for (int nb = 0; nb < 16; nb++) {
        int c = c0 + nb * 8;
        *(float2*)&g_part[b][r0][c]     = make_float2(acc[nb][0], acc[nb][1]);
        *(float2*)&g_part[b][r0 + 8][c] = make_float2(acc[nb][2], acc[nb][3]);
    }

    // ---- self-clean: zero OWN disjoint slice of counts/outdeg for next call ----
    uint4 zu = make_uint4(0u, 0u, 0u, 0u);
    for (int i = tid; i < NB * 4; i += 512) {
        int n = n0 + (i >> 2);
        if (n < NNODES) ((uint4*)g_Cp)[n * 4 + (i & 3)] = zu;
    }
    for (int i = tid; i < NB; i += 512) {
        int n = n0 + i;
        if (n < NNODES) g_outdeg[n] = 0;
    }
    if (b == 0) {
        if (tid < NG) { g_cntR[tid] = g_cnt[tid]; g_cnt[tid] = 0; }
        if (tid >= 64 && tid < 68) g_tbar[tid - 64] = 0u;   // reset tail barriers
    }
}

// tail: fold partials -> XF, then 3 head layers, barrier-synced (all phases short+uniform)
__global__ void __launch_bounds__(256, 1)
tail_k(const float* __restrict__ W0, const float* __restrict__ b0p,
       const float* __restrict__ W1, const float* __restrict__ b1p,
       const float* __restrict__ W2, const float* __restrict__ b2p,
       float* __restrict__ out) {
    __shared__ float As[16][17];
    __shared__ float Ws[16][17];
    int b   = blockIdx.x;
    int tid = threadIdx.x;

    auto gbar = [&](int i) {
        __syncthreads();
        __threadfence();
        if (tid == 0) {
            atomicAdd((unsigned*)&g_tbar[i], 1u);
            while (g_tbar[i] < (unsigned)TCTA) { }
        }
        __syncthreads();
        __threadfence();
    };

    // ---- phase 0: fold 140 partials for row m=b, normalize, write XF ----
    {
        int m = b, f = tid;
        const float* p = &g_part[0][m][f];
        float acc = 0.f;
#pragma unroll
        for (int q0 = 0; q0 < KPADB; q0 += 28) {
            float v[28];
#pragma unroll
            for (int q = 0; q < 28; q++) v[q] = p[(size_t)(q0 + q) * 128 * IND];
            float s0 = 0.f, s1 = 0.f, s2 = 0.f, s3 = 0.f;
#pragma unroll
            for (int q = 0; q < 28; q += 4) {
                s0 += v[q]; s1 += v[q + 1]; s2 += v[q + 2]; s3 += v[q + 3];
            }
            acc += (s0 + s1) + (s2 + s3);
        }
        int g = m & (NG - 1);
        int cnt = g_cntR[g];
        float inv = cnt > 0 ? 1.0f / (float)cnt : 0.0f;
        int row = (m < NG) ? (NG + m) : (m - NG);   // dst -> 64.., src -> 0..
        g_XF[row][f] = acc * inv;
    }
    gbar(0);

    // ---- phases 1-3: head layers (64 CTAs active, all arrive at barriers) ----
#pragma unroll
    for (int layer = 0; layer < 3; layer++) {
        if (b < 64) {
            int rt = b >> 3, ct = b & 7;
            int ty = tid >> 4, tx = tid & 15;
            int r  = rt * 16 + ty;
            int c  = ct * 16 + tx;
            const float* A  = (layer == 0) ? &g_XF[0][0]
                             : (layer == 1) ? &g_P[0][0][0] : &g_P[1][0][0];
            const float* W  = (layer == 0) ? W0 : (layer == 1) ? W1 : W2;
            const float* bs = (layer == 0) ? b0p : (layer == 1) ? b1p : b2p;
            int K = (layer == 0) ? IND : HID;
            float acc = 0.f;
            for (int k0 = 0; k0 < K; k0 += 16) {
                As[ty][tx] = A[r * K + k0 + tx];
                Ws[ty][tx] = W[(k0 + ty) * HID + c];
                __syncthreads();
#pragma unroll
                for (int kk = 0; kk < 16; kk++) acc += As[ty][kk] * Ws[kk][tx];
                __syncthreads();
            }
            int g = r & (NG - 1);
            float flag = g_cntR[g] > 0 ? 1.0f : 0.0f;
            float v = (acc + bs[c]) * flag;
            if (layer < 2) g_P[layer][r * HID + c - r * HID + c >= 0 ? 0 : 0], g_P[layer][r][c] = v;
            int col = layer * 256 + ((r < NG) ? 0 : HID) + c;
            out[g * 768 + col] = v;
        }
        if (layer < 2) gbar(layer + 1);
    }
}

// ---------------- launcher ----------------
extern "C" void kernel_launch(void* const* d_in, const int* in_sizes, int n_in,
                              void* d_out, int out_size) {
    const float* x     = (const float*)d_in[0];
    const int*   eidx  = (const int*)d_in[1];
    const int*   batch = (const int*)d_in[2];
    const float* W0 = (const float*)d_in[3];
    const float* b0 = (const float*)d_in[4];
    const float* W1 = (const float*)d_in[5];
    const float* b1 = (const float*)d_in[6];
    const float* W2 = (const float*)d_in[7];
    const float* b2 = (const float*)d_in[8];
    float* out = (float*)d_out;

    const int* src = eidx;
    const int* dst = eidx + NEDGES;

    count_k<<<NEDGES / 4 / 256, 256>>>(src, dst, batch);
    mm_k<<<KBLK, 512>>>(x, batch);
    tail_k<<<TCTA, 256>>>(W0, b0, W1, b1, W2, b2, out);
}

// round 13
// speedup vs baseline: 1.6046x; 1.0081x over previous
#include <cuda_runtime.h>
#include <cuda_bf16.h>
#include <cstdint>

#define NNODES 20000
#define NEDGES 640000
#define IND    256
#define HID    128
#define NG     64

#define KBLK   139          // CTAs in split-K GEMM
#define KPADB  140          // padded partial count (index 139 stays zero forever)
#define NB     144          // nodes per CTA
#define NST    9            // stages of 16 nodes
#define TCTA   128          // tail_k CTAs

// ---------------- device scratch (zero-initialized at module load) ----------------
__device__ __align__(16) unsigned g_Cp[NNODES * 16];       // packed u8 counts [node][g]
__device__ __align__(16) int      g_outdeg[NNODES];
__device__ __align__(16) int      g_cnt[NG];               // atomic accumulator (self-cleaned)
__device__ __align__(16) int      g_cntR[NG];              // stable copy read by tail
__device__ __align__(16) float    g_part[KPADB][128][IND]; // split-K partials
__device__ __align__(16) float    g_XF[128][IND];          // pooled features
__device__ __align__(16) float    g_P[2][128][HID];        // layer activations
__device__ volatile unsigned      g_tbar[4];               // tail barriers (reset by mm_k)

// ---------------- helpers ----------------
__device__ __forceinline__ uint32_t f2tf32(float v) {
    uint32_t t;
    asm("cvt.rna.tf32.f32 %0, %1;" : "=r"(t) : "f"(v));
    return t;
}
__device__ __forceinline__ void mma_tf32(float* d, uint32_t a0, uint32_t a1, uint32_t a2,
                                         uint32_t a3, uint32_t b0, uint32_t b1) {
    asm volatile(
        "mma.sync.aligned.m16n8k8.row.col.f32.tf32.tf32.f32 "
        "{%0,%1,%2,%3},{%4,%5,%6,%7},{%8,%9},{%0,%1,%2,%3};"
        : "+f"(d[0]), "+f"(d[1]), "+f"(d[2]), "+f"(d[3])
        : "r"(a0), "r"(a1), "r"(a2), "r"(a3), "r"(b0), "r"(b1));
}
// B smem layout (verified R9): element (k, n) of the 16x256 x-tile
__device__ __forceinline__ uint32_t bofB(int k, int n) {
    int nq  = n & 7;
    int nb  = n >> 3;
    int blk = ((nb >> 2) ^ nq ^ ((k & 3) << 1)) & 7;
    return (uint32_t)(k * 1024 + nq * 128 + blk * 16 + (nb & 3) * 4);
}
// A smem layout (verified R9): transposed [k][m]
__device__ __forceinline__ uint32_t bofA(int k, int m) {
    int mb  = m >> 2;
    int blk = (mb & 24) | (((mb & 7) ^ ((k & 3) << 1)) & 7);
    return (uint32_t)(k * 512 + blk * 16 + (m & 3) * 4);
}

// ---------------- kernels ----------------
// 8 edges per thread: all gathers issued before any atomic (MLP 8)
__global__ void count_k(const int* __restrict__ src, const int* __restrict__ dst,
                        const int* __restrict__ batch) {
    __shared__ int hist[NG];
    int t = threadIdx.x;
    if (t < NG) hist[t] = 0;
    __syncthreads();
    int gid = blockIdx.x * blockDim.x + t;     // one thread = 8 edges
    if (gid < NEDGES / 8) {
        int4 s0 = ((const int4*)src)[gid * 2];
        int4 s1 = ((const int4*)src)[gid * 2 + 1];
        int4 d0 = ((const int4*)dst)[gid * 2];
        int4 d1 = ((const int4*)dst)[gid * 2 + 1];
        int ss[8] = {s0.x, s0.y, s0.z, s0.w, s1.x, s1.y, s1.z, s1.w};
        int dd[8] = {d0.x, d0.y, d0.z, d0.w, d1.x, d1.y, d1.z, d1.w};
        int gg[8];
#pragma unroll
        for (int u = 0; u < 8; u++) gg[u] = batch[ss[u]];   // 8 independent gathers
#pragma unroll
        for (int u = 0; u < 8; u++)
            atomicAdd(&g_Cp[dd[u] * 16 + (gg[u] >> 2)], 1u << ((gg[u] & 3) * 8));
#pragma unroll
        for (int u = 0; u < 8; u++) atomicAdd(&g_outdeg[ss[u]], 1);
#pragma unroll
        for (int u = 0; u < 8; u++) atomicAdd(&hist[gg[u]], 1);
    }
    __syncthreads();
    if (t < NG && hist[t]) atomicAdd(&g_cnt[t], hist[t]);
}

// TF32 pooling GEMM (verified R9) + self-cleaning epilogue
__global__ void __launch_bounds__(512, 1) mm_k(const float* __restrict__ x,
                                               const int* __restrict__ batch) {
    __shared__ __align__(16) float Bsm[2][16 * 256];
    __shared__ __align__(16) float Atr[2][16 * 128];

    const uint8_t* C8 = (const uint8_t*)g_Cp;
    int b    = blockIdx.x;
    int n0   = b * NB;
    int tid  = threadIdx.x;
    int lane = tid & 31;
    int warp = tid >> 5;
    int wm   = warp & 7;
    int wn   = warp >> 3;
    int kq   = lane & 3;
    int r8   = lane >> 2;

    int kx = warp;
    int cx = lane;
    int ma = tid & 127;
    int kh = tid >> 7;

    float acc[16][4];
#pragma unroll
    for (int i = 0; i < 16; i++)
#pragma unroll
        for (int j = 0; j < 4; j++) acc[i][j] = 0.f;

    const float4* x4 = (const float4*)x;

    float4 pv0, pv1;
    float  pa[4];
    auto prefetch = [&](int s) {
        int nx = n0 + s * 16 + kx;
        if (nx < NNODES) {
            pv0 = x4[(size_t)nx * 64 + cx * 2];
            pv1 = x4[(size_t)nx * 64 + cx * 2 + 1];
        } else {
            pv0 = make_float4(0.f, 0.f, 0.f, 0.f);
            pv1 = pv0;
        }
#pragma unroll
        for (int j = 0; j < 4; j++) {
            int na = n0 + s * 16 + kh * 4 + j;
            float v = 0.f;
            if (na < NNODES) {
                if (ma < NG) {
                    v = (float)C8[na * 64 + ma];
                } else {
                    int g = ma - NG;
                    if (batch[na] == g) v = (float)g_outdeg[na];
                }
            }
            pa[j] = v;
        }
    };
    auto stage = [&](int buf) {
        float vs[8] = {pv0.x, pv0.y, pv0.z, pv0.w, pv1.x, pv1.y, pv1.z, pv1.w};
        char* Bb = (char*)Bsm[buf];
        char* Ab = (char*)Atr[buf];
#pragma unroll
        for (int j = 0; j < 8; j++)
            *(uint32_t*)(Bb + bofB(kx, cx * 8 + j)) = f2tf32(vs[j]);
#pragma unroll
        for (int j = 0; j < 4; j++)
            *(uint32_t*)(Ab + bofA(kh * 4 + j, ma)) = f2tf32(pa[j]);
    };

    prefetch(0);
    stage(0);

    for (int s = 0; s < NST; s++) {
        __syncthreads();
        int buf = s & 1;
        if (s + 1 < NST) prefetch(s + 1);

        const char* Ab = (const char*)Atr[buf];
        const char* Bb = (const char*)Bsm[buf];
#pragma unroll
        for (int ko = 0; ko < 16; ko += 8) {
            uint32_t a0 = *(const uint32_t*)(Ab + bofA(ko + kq,     wm * 16 + r8));
            uint32_t a1 = *(const uint32_t*)(Ab + bofA(ko + kq,     wm * 16 + r8 + 8));
            uint32_t a2 = *(const uint32_t*)(Ab + bofA(ko + 4 + kq, wm * 16 + r8));
            uint32_t a3 = *(const uint32_t*)(Ab + bofA(ko + 4 + kq, wm * 16 + r8 + 8));
#pragma unroll
            for (int g0 = 0; g0 < 4; g0++) {
                int nbase = (wn * 16 + g0 * 4) * 8 + r8;
                float4 f0 = *(const float4*)(Bb + bofB(ko + kq,     nbase));
                float4 f1 = *(const float4*)(Bb + bofB(ko + 4 + kq, nbase));
                const float b0v[4] = {f0.x, f0.y, f0.z, f0.w};
                const float b1v[4] = {f1.x, f1.y, f1.z, f1.w};
#pragma unroll
                for (int t = 0; t < 4; t++) {
                    mma_tf32(acc[g0 * 4 + t], a0, a1, a2, a3,
                             __float_as_uint(b0v[t]), __float_as_uint(b1v[t]));
                }
            }
        }
        if (s + 1 < NST) stage((s + 1) & 1);
    }

    int r0 = wm * 16 + r8;
    int c0 = wn * 128 + kq * 2;
#pragma unroll
    for (int nb = 0; nb < 16; nb++) {
        int c = c0 + nb * 8;
        *(float2*)&g_part[b][r0][c]     = make_float2(acc[nb][0], acc[nb][1]);
        *(float2*)&g_part[b][r0 + 8][c] = make_float2(acc[nb][2], acc[nb][3]);
    }

    // ---- self-clean: zero OWN disjoint slice of counts/outdeg for next call ----
    uint4 zu = make_uint4(0u, 0u, 0u, 0u);
    for (int i = tid; i < NB * 4; i += 512) {
        int n = n0 + (i >> 2);
        if (n < NNODES) ((uint4*)g_Cp)[n * 4 + (i & 3)] = zu;
    }
    for (int i = tid; i < NB; i += 512) {
        int n = n0 + i;
        if (n < NNODES) g_outdeg[n] = 0;
    }
    if (b == 0) {
        if (tid < NG) { g_cntR[tid] = g_cnt[tid]; g_cnt[tid] = 0; }
        if (tid >= 64 && tid < 68) g_tbar[tid - 64] = 0u;   // reset tail barriers
    }
}

// tail: fold partials -> XF (float4, 4-way depth split), then 3 head layers
__global__ void __launch_bounds__(256, 1)
tail_k(const float* __restrict__ W0, const float* __restrict__ b0p,
       const float* __restrict__ W1, const float* __restrict__ b1p,
       const float* __restrict__ W2, const float* __restrict__ b2p,
       float* __restrict__ out) {
    __shared__ float As[16][17];
    __shared__ float Ws[16][17];
    __shared__ float4 red[4][64];
    int b   = blockIdx.x;
    int tid = threadIdx.x;

    auto gbar = [&](int i) {
        __syncthreads();
        __threadfence();
        if (tid == 0) {
            atomicAdd((unsigned*)&g_tbar[i], 1u);
            while (g_tbar[i] < (unsigned)TCTA) { }
        }
        __syncthreads();
        __threadfence();
    };

    // ---- phase 0: fold 140 partials for row m=b (float4, depth quarters of 35) ----
    {
        int m  = b;
        int f4 = tid & 63;      // float4 column group
        int qq = tid >> 6;      // depth quarter 0..3
        const float4* p = (const float4*)&g_part[qq * 35][m][f4 * 4];
        const size_t stride4 = (size_t)128 * IND / 4;     // float4s between partials
        float4 acc = make_float4(0.f, 0.f, 0.f, 0.f);
#pragma unroll
        for (int q0 = 0; q0 < 35; q0 += 7) {
            float4 v[7];
#pragma unroll
            for (int q = 0; q < 7; q++) v[q] = p[(size_t)(q0 + q) * stride4];
#pragma unroll
            for (int q = 0; q < 7; q++) {
                acc.x += v[q].x; acc.y += v[q].y; acc.z += v[q].z; acc.w += v[q].w;
            }
        }
        red[qq][f4] = acc;
        __syncthreads();
        if (qq == 0) {
            float4 a0 = red[0][f4], a1 = red[1][f4], a2 = red[2][f4], a3 = red[3][f4];
            float4 s;
            s.x = (a0.x + a1.x) + (a2.x + a3.x);
            s.y = (a0.y + a1.y) + (a2.y + a3.y);
            s.z = (a0.z + a1.z) + (a2.z + a3.z);
            s.w = (a0.w + a1.w) + (a2.w + a3.w);
            int g = m & (NG - 1);
            int cnt = g_cntR[g];
            float inv = cnt > 0 ? 1.0f / (float)cnt : 0.0f;
            s.x *= inv; s.y *= inv; s.z *= inv; s.w *= inv;
            int row = (m < NG) ? (NG + m) : (m - NG);   // dst -> 64.., src -> 0..
            ((float4*)&g_XF[row][0])[f4] = s;
        }
    }
    gbar(0);

    // ---- phases 1-3: head layers (64 CTAs active) ----
#pragma unroll
    for (int layer = 0; layer < 3; layer++) {
        if (b < 64) {
            int rt = b >> 3, ct = b & 7;
            int ty = tid >> 4, tx = tid & 15;
            int r  = rt * 16 + ty;
            int c  = ct * 16 + tx;
            const float* A  = (layer == 0) ? &g_XF[0][0]
                             : (layer == 1) ? &g_P[0][0][0] : &g_P[1][0][0];
            const float* W  = (layer == 0) ? W0 : (layer == 1) ? W1 : W2;
            const float* bs = (layer == 0) ? b0p : (layer == 1) ? b1p : b2p;
            int K = (layer == 0) ? IND : HID;
            float acc = 0.f;
            for (int k0 = 0; k0 < K; k0 += 16) {
                As[ty][tx] = A[r * K + k0 + tx];
                Ws[ty][tx] = W[(k0 + ty) * HID + c];
                __syncthreads();
#pragma unroll
                for (int kk = 0; kk < 16; kk++) acc += As[ty][kk] * Ws[kk][tx];
                __syncthreads();
            }
            int g = r & (NG - 1);
            float flag = g_cntR[g] > 0 ? 1.0f : 0.0f;
            float v = (acc + bs[c]) * flag;
            if (layer < 2) g_P[layer][r][c] = v;
            int col = layer * 256 + ((r < NG) ? 0 : HID) + c;
            out[g * 768 + col] = v;
        }
        if (layer < 2) gbar(layer + 1);
    }
}

// ---------------- launcher ----------------
extern "C" void kernel_launch(void* const* d_in, const int* in_sizes, int n_in,
                              void* d_out, int out_size) {
    const float* x     = (const float*)d_in[0];
    const int*   eidx  = (const int*)d_in[1];
    const int*   batch = (const int*)d_in[2];
    const float* W0 = (const float*)d_in[3];
    const float* b0 = (const float*)d_in[4];
    const float* W1 = (const float*)d_in[5];
    const float* b1 = (const float*)d_in[6];
    const float* W2 = (const float*)d_in[7];
    const float* b2 = (const float*)d_in[8];
    float* out = (float*)d_out;

    const int* src = eidx;
    const int* dst = eidx + NEDGES;

    count_k<<<(NEDGES / 8 + 255) / 256, 256>>>(src, dst, batch);
    mm_k<<<KBLK, 512>>>(x, batch);
    tail_k<<<TCTA, 256>>>(W0, b0, W1, b1, W2, b2, out);
}